// round 4
// baseline (speedup 1.0000x reference)
#include <cuda_runtime.h>
#include <cstdint>

// CRF_76501957476894 — CRF loss forward algorithm.
// B=512 batches, N=1024 timesteps, K=64 states.
// One warp per batch (128 CTAs x 128 thr = 1 warp/SMSP on 128 SMs).
// Lane l owns states (2l, 2l+1).
// Exp-domain recurrence: a_new[j] = (sum_i a[i]*E[i][j]) * exp(emit[j]),
// E = exp(trans) held in 64 packed f32x2 registers per lane.
// Normalization (a /= sum(a), M += log(sum)) every 4 steps.
// Software pipeline: LDG of group g+1 issues one full group (~600 cyc) before
// its exp/score processing, which in turn is one group before MATVEC use.

#define FULLMASK 0xFFFFFFFFu

__device__ __forceinline__ unsigned long long pk2(float x, float y) {
    unsigned long long r;
    asm("mov.b64 %0, {%1, %2};" : "=l"(r) : "f"(x), "f"(y));
    return r;
}
__device__ __forceinline__ void upk2(unsigned long long p, float &x, float &y) {
    asm("mov.b64 {%0, %1}, %2;" : "=f"(x), "=f"(y) : "l"(p));
}

// One forward step: matvec in exp domain + emit multiply + optional renorm + share.
#define MATVEC_STEP(EE, RB, WB, DONORM) do {                                          \
    unsigned long long acc[4] = {0ull, 0ull, 0ull, 0ull};                             \
    _Pragma("unroll")                                                                 \
    for (int i_ = 0; i_ < 64; i_ += 2) {                                              \
        unsigned long long p0_, p1_;                                                  \
        asm volatile("ld.shared.v2.b64 {%0,%1}, [%2];"                                \
                     : "=l"(p0_), "=l"(p1_) : "r"((RB) + 8u * i_));                   \
        asm("fma.rn.f32x2 %0, %1, %2, %0;"                                            \
            : "+l"(acc[i_ & 3]) : "l"(p0_), "l"(E2[i_]));                             \
        asm("fma.rn.f32x2 %0, %1, %2, %0;"                                            \
            : "+l"(acc[(i_ + 1) & 3]) : "l"(p1_), "l"(E2[i_ + 1]));                   \
    }                                                                                 \
    unsigned long long v01_, v23_, vv_, an_;                                          \
    asm("add.rn.f32x2 %0, %1, %2;" : "=l"(v01_) : "l"(acc[0]), "l"(acc[1]));          \
    asm("add.rn.f32x2 %0, %1, %2;" : "=l"(v23_) : "l"(acc[2]), "l"(acc[3]));          \
    asm("add.rn.f32x2 %0, %1, %2;" : "=l"(vv_)  : "l"(v01_),  "l"(v23_));             \
    asm("mul.rn.f32x2 %0, %1, %2;" : "=l"(an_)  : "l"(vv_),   "l"(EE));               \
    upk2(an_, a0, a1);                                                                \
    if (DONORM) {                                                                     \
        float s_ = a0 + a1;                                                           \
        _Pragma("unroll")                                                             \
        for (int o_ = 16; o_ > 0; o_ >>= 1) s_ += __shfl_xor_sync(FULLMASK, s_, o_);  \
        float r_; asm("rcp.approx.f32 %0, %1;" : "=f"(r_) : "f"(s_));                 \
        M += __logf(s_);                                                              \
        a0 *= r_; a1 *= r_;                                                           \
    }                                                                                 \
    asm volatile("st.shared.v4.b32 [%0], {%1,%1,%2,%2};" ::                           \
        "r"((WB) + 16u * l), "r"(__float_as_uint(a0)), "r"(__float_as_uint(a1)));     \
    __syncwarp();                                                                     \
} while (0)

// Issue loads for timestep T into raw registers (no consumption here!).
#define LOAD_T(T, ER, YR_) do {                                                       \
    (ER)  = *reinterpret_cast<const float2*>(yp + (size_t)(T) * 64 + 2 * l);          \
    (YR_) = __ldg(yr + (T));                                                          \
} while (0)

// Process previously-loaded raws: fold point/trans scores, compute exp(emit).
// ts uses a warp-uniform broadcast LDS (all lanes accumulate identically).
#define PROC_T(ER, YR_, DST) do {                                                     \
    point += (((YR_) >> 1) == l) ? (((YR_) & 1) ? (ER).y : (ER).x) : 0.0f;            \
    ts += tsh[yprev * 64 + (YR_)];                                                    \
    yprev = (YR_);                                                                    \
    (DST) = pk2(__expf((ER).x), __expf((ER).y));                                      \
} while (0)

__global__ void __launch_bounds__(128, 1) crf_fwd_kernel(
    const float* __restrict__ y_pred,   // [512,1024,64]
    const float* __restrict__ trans,    // [64,64]
    const int*   __restrict__ y_true,   // [512,1024]
    float*       __restrict__ out)      // [512]
{
    __shared__ float  tsh[64 * 64];
    __shared__ float2 adup[4][2][64];   // per-warp double-buffered duplicated-a

    const int tid = threadIdx.x;
    const int w = tid >> 5;
    const int l = tid & 31;

    for (int i = tid; i < 4096; i += 128) tsh[i] = trans[i];
    __syncthreads();

    const int b = blockIdx.x * 4 + w;
    const float* yp = y_pred + (size_t)b * (1024 * 64);
    const int*   yr = y_true + b * 1024;

    // E2[i] = packed ( exp(trans[i][2l]), exp(trans[i][2l+1]) ), 128 registers.
    unsigned long long E2[64];
    #pragma unroll
    for (int i = 0; i < 64; i++) {
        float e0 = __expf(tsh[i * 64 + 2 * l]);
        float e1 = __expf(tsh[i * 64 + 2 * l + 1]);
        E2[i] = pk2(e0, e1);
    }

    const uint32_t shbase = (uint32_t)__cvta_generic_to_shared(&adup[w][0][0]);
    const uint32_t buf0 = shbase;
    const uint32_t buf1 = shbase + 512u;

    // ---- t = 0 init ----
    float2 e0v = *reinterpret_cast<const float2*>(yp + 2 * l);
    int yprev = __ldg(yr);
    float point = ((yprev >> 1) == l) ? ((yprev & 1) ? e0v.y : e0v.x) : 0.0f;
    float ts = 0.0f;   // trans score: warp-uniform accumulation, lane 0's copy used.
    float a0 = __expf(e0v.x);
    float a1 = __expf(e0v.y);
    float M  = 0.0f;
    asm volatile("st.shared.v4.b32 [%0], {%1,%1,%2,%2};" ::
        "r"(buf0 + 16u * l), "r"(__float_as_uint(a0)), "r"(__float_as_uint(a1)));
    __syncwarp();

    // Pipeline state: raw holds loads for the NEXT group to be processed;
    // ee holds exp/scores for the NEXT group to be consumed by MATVEC.
    float2 raw[4];
    int    yraw[4];
    unsigned long long ee[4];

    // Prologue: load G0 (t=1..4); process G0; load G1 (t=5..8).
    #pragma unroll
    for (int k = 0; k < 4; k++) LOAD_T(1 + k, raw[k], yraw[k]);
    #pragma unroll
    for (int k = 0; k < 4; k++) PROC_T(raw[k], yraw[k], ee[k]);
    #pragma unroll
    for (int k = 0; k < 4; k++) LOAD_T(5 + k, raw[k], yraw[k]);

    // ---- main loop: 253 iters. Iter g: process G_{g+1} (loaded last iter),
    //      issue loads for G_{g+2} (t <= 1020), MATVEC group G_g, rotate. ----
    #pragma unroll 1
    for (int g = 0; g < 253; ++g) {
        unsigned long long en[4];
        #pragma unroll
        for (int k = 0; k < 4; k++) PROC_T(raw[k], yraw[k], en[k]);
        const int tb = 9 + 4 * g;                       // G_{g+2}: t = tb..tb+3, max 1020
        #pragma unroll
        for (int k = 0; k < 4; k++) LOAD_T(tb + k, raw[k], yraw[k]);
        MATVEC_STEP(ee[0], buf0, buf1, false);
        MATVEC_STEP(ee[1], buf1, buf0, false);
        MATVEC_STEP(ee[2], buf0, buf1, false);
        MATVEC_STEP(ee[3], buf1, buf0, true);           // renorm every 4 steps
        ee[0] = en[0]; ee[1] = en[1]; ee[2] = en[2]; ee[3] = en[3];
    }

    // ---- epilogue 1: ee = G253 (t=1013..1016), raw = G254 loads (t=1017..1020) ----
    unsigned long long en[4];
    #pragma unroll
    for (int k = 0; k < 4; k++) PROC_T(raw[k], yraw[k], en[k]);
    float2 rt3[3]; int yt3[3];
    #pragma unroll
    for (int k = 0; k < 3; k++) LOAD_T(1021 + k, rt3[k], yt3[k]);   // tail loads
    MATVEC_STEP(ee[0], buf0, buf1, false);
    MATVEC_STEP(ee[1], buf1, buf0, false);
    MATVEC_STEP(ee[2], buf0, buf1, false);
    MATVEC_STEP(ee[3], buf1, buf0, true);

    // ---- epilogue 2: G254 (t=1017..1020); process tail exps ----
    unsigned long long et[3];
    #pragma unroll
    for (int k = 0; k < 3; k++) PROC_T(rt3[k], yt3[k], et[k]);
    MATVEC_STEP(en[0], buf0, buf1, false);
    MATVEC_STEP(en[1], buf1, buf0, false);
    MATVEC_STEP(en[2], buf0, buf1, false);
    MATVEC_STEP(en[3], buf1, buf0, true);

    // ---- tail: t = 1021..1023 ----
    MATVEC_STEP(et[0], buf0, buf1, false);
    MATVEC_STEP(et[1], buf1, buf0, false);
    MATVEC_STEP(et[2], buf0, buf1, false);

    // ---- finalize ----
    float s = a0 + a1;
    #pragma unroll
    for (int o = 16; o > 0; o >>= 1) s += __shfl_xor_sync(FULLMASK, s, o);
    float log_norm = M + __logf(s);

    #pragma unroll
    for (int o = 16; o > 0; o >>= 1) point += __shfl_xor_sync(FULLMASK, point, o);

    if (l == 0) out[b] = log_norm - (point + ts);
}

extern "C" void kernel_launch(void* const* d_in, const int* in_sizes, int n_in,
                              void* d_out, int out_size) {
    const float* y_pred = (const float*)d_in[0];   // [512,1024,64] f32
    const float* trans  = (const float*)d_in[1];   // [64,64] f32
    const int*   y_true = (const int*)d_in[2];     // [512,1024] i32
    float* out = (float*)d_out;                    // [512] f32
    (void)in_sizes; (void)n_in; (void)out_size;
    crf_fwd_kernel<<<128, 128>>>(y_pred, trans, y_true, out);
}